// round 5
// baseline (speedup 1.0000x reference)
#include <cuda_runtime.h>
#include <cstdio>

// VoConstruction: out = Re( O @ (Umat d Umat^H) ), algebraically reduced.
// Harness world is all-float32: complex64 reference tensors are cast to
// float32 (real part) both for the O input (4 floats) and the output
// ([B,2,2] -> 4 floats per batch element).
//
// Derivation (A=diag(e^{ip},e^{-ip}), Brot(theta), C=diag(e^{id},e^{-id})):
//   C d C^H = d exactly  -> delta = U[:,2] cancels, never loaded.
//   H00 = (l1+l2) + (l1-l2)cos2t                  (real)
//   H11 = (l1+l2) - (l1-l2)cos2t                  (real)
//   H01 = (l2-l1) sin2t e^{2i psi} = hr + i*hi,   H10 = conj
// O is real (imag discarded by the float32 cast), so:
//   Re(O@H) = O * [[H00, hr],[hr, H11]]

__global__ __launch_bounds__(256)
void vo_kernel(const float* __restrict__ U,
               const float* __restrict__ x1,
               const float* __restrict__ x2,
               const float* __restrict__ O4,   // 4 floats: real part of O, row-major
               float4* __restrict__ out,        // [B] float4 = [B,2,2] float32
               int n)
{
    int b = blockIdx.x * blockDim.x + threadIdx.x;
    if (b >= n) return;

    float psi   = U[3 * b + 0];
    float theta = U[3 * b + 1];
    // U[3*b+2] (delta) cancels exactly — not loaded.

    float l1 = x1[b];
    float l2 = x2[b] * (1.0f - fabsf(l1));

    float s2t, c2t, s2p, c2p;
    sincosf(2.0f * theta, &s2t, &c2t);
    sincosf(2.0f * psi,   &s2p, &c2p);

    float sum = l1 + l2;
    float dif = l1 - l2;

    float H00 = fmaf(dif,  c2t, sum);   // real
    float H11 = fmaf(-dif, c2t, sum);   // real
    float hr  = (-dif * s2t) * c2p;     // Re(H01) = Re(H10)

    float o00 = O4[0], o01 = O4[1], o10 = O4[2], o11 = O4[3];

    float r00 = fmaf(o00, H00, o01 * hr);
    float r01 = fmaf(o00, hr,  o01 * H11);
    float r10 = fmaf(o10, H00, o11 * hr);
    float r11 = fmaf(o10, hr,  o11 * H11);

    out[b] = make_float4(r00, r01, r10, r11);
}

extern "C" void kernel_launch(void* const* d_in, const int* in_sizes, int n_in,
                              void* d_out, int out_size)
{
    // diag (surfaced on failure)
    fprintf(stderr, "kl-diag: n_in=%d out_size=%d sizes=[", n_in, out_size);
    for (int i = 0; i < n_in; i++) fprintf(stderr, "%d%s", in_sizes[i], i + 1 < n_in ? "," : "");
    fprintf(stderr, "]\n");
    fflush(stderr);

    // Confirmed layout: d_in = { U[3B] f32, x1[B] f32, x2[B] f32, O[4] f32 }.
    const float* U  = (const float*)d_in[0];
    const float* x1 = (const float*)d_in[1];
    const float* x2 = (const float*)d_in[2];
    const float* O4 = (const float*)d_in[3];

    long n = in_sizes[0] / 3;
    long n_out = (long)out_size / 4;   // out is float32, 4 per batch element
    if (n_out < n) n = n_out;
    if (n <= 0) return;

    float4* out = (float4*)d_out;
    int threads = 256;
    int blocks = (int)((n + threads - 1) / threads);
    vo_kernel<<<blocks, threads>>>(U, x1, x2, O4, out, (int)n);
}